// round 1
// baseline (speedup 1.0000x reference)
#include <cuda_runtime.h>
#include <math.h>

#define BB   4
#define C8   8
#define C16  16
#define FF   256
#define TN   2000
#define CHW  (FF*TN)          // 512000 elems per (b,ri,ch) plane
#define TWO_PI_F     6.283185307179586f
#define INV_TWO_PI_F 0.15915494309189535f

// Scratch (static __device__ to satisfy allocation guards)
__device__ float g_s1[BB*2*C16*CHW];   // after cLog+cs+cAct   (262 MB)
__device__ float g_s2[BB*2*C16*CHW];   // after fc+cAct        (262 MB)

__device__ __forceinline__ float mod2pi(float a) {
    // jnp.mod(a, 2*pi): floor-mod
    return a - floorf(a * INV_TWO_PI_F) * TWO_PI_F;
}

// ---------------------------------------------------------------------------
// Kernel A: cLog -> channel_shuffle (per-freq 8->16, separate r/i) -> cAct
// grid: (t_chunks, FF, BB), block 256 over t
// ---------------------------------------------------------------------------
__global__ void kA(const float* __restrict__ x,
                   const float* __restrict__ wr, const float* __restrict__ wi,
                   const float* __restrict__ br, const float* __restrict__ bi)
{
    const int f = blockIdx.y;
    const int b = blockIdx.z;
    const int t = blockIdx.x * blockDim.x + threadIdx.x;

    __shared__ float swr[C16*C8], swi[C16*C8], sbr[C16], sbi[C16];
    for (int i = threadIdx.x; i < C16*C8; i += blockDim.x) {
        swr[i] = wr[f*C16*C8 + i];
        swi[i] = wi[f*C16*C8 + i];
    }
    if (threadIdx.x < C16) {
        sbr[threadIdx.x] = br[f*C16 + threadIdx.x];
        sbi[threadIdx.x] = bi[f*C16 + threadIdx.x];
    }
    __syncthreads();
    if (t >= TN) return;

    const int off = f*TN + t;
    float lm[C8], ph[C8];
    #pragma unroll
    for (int c = 0; c < C8; c++) {
        float xr = x[((b*2+0)*C8 + c)*CHW + off];
        float xi = x[((b*2+1)*C8 + c)*CHW + off];
        // log(sqrt(r^2+i^2+1e-12)) == 0.5*log(r^2+i^2+1e-12)
        lm[c] = 0.5f * __logf(fmaf(xr, xr, fmaf(xi, xi, 1e-12f)));
        ph[c] = atan2f(xi, xr);
    }
    #pragma unroll
    for (int o = 0; o < C16; o++) {
        float sr = sbr[o], si = sbi[o];
        #pragma unroll
        for (int c = 0; c < C8; c++) {
            sr = fmaf(swr[o*C8+c], lm[c], sr);
            si = fmaf(swi[o*C8+c], ph[c], si);
        }
        float w = (__cosf(si) + 1.0f) * 0.5f;
        g_s1[((b*2+0)*C16 + o)*CHW + off] = w * sr;
        g_s1[((b*2+1)*C16 + o)*CHW + off] = mod2pi(si);
    }
}

// ---------------------------------------------------------------------------
// Kernel B: freq_conv (depthwise over freq, k=5, pad=2, separate r/i) -> cAct
// grid: (t_chunks, FF, BB*C16), block 256 over t
// ---------------------------------------------------------------------------
__global__ void kB(const float* __restrict__ wr, const float* __restrict__ wi,
                   const float* __restrict__ br, const float* __restrict__ bi)
{
    const int f  = blockIdx.y;
    const int bc = blockIdx.z;
    const int b  = bc / C16;
    const int c  = bc % C16;
    const int t  = blockIdx.x * blockDim.x + threadIdx.x;
    if (t >= TN) return;

    const int base_r = ((b*2+0)*C16 + c)*CHW;
    const int base_i = ((b*2+1)*C16 + c)*CHW;

    float yr = br[c];
    float yi = bi[c];
    #pragma unroll
    for (int j = 0; j < 5; j++) {
        int ff = f + j - 2;
        if (ff >= 0 && ff < FF) {
            yr = fmaf(wr[c*5 + j], g_s1[base_r + ff*TN + t], yr);
            yi = fmaf(wi[c*5 + j], g_s1[base_i + ff*TN + t], yi);
        }
    }
    float w = (__cosf(yi) + 1.0f) * 0.5f;
    g_s2[base_r + f*TN + t] = w * yr;
    g_s2[base_i + f*TN + t] = mod2pi(yi);
}

// ---------------------------------------------------------------------------
// Kernel C: time_conv (per-freq 16->8, taps t+2k) -> cExp -> last_shuffle
//           (complex 8x8) -> cMul(x) -> last (complex 8x8) -> out
// grid: BB*FF blocks, block 512 looping over t
// ---------------------------------------------------------------------------
__global__ void __launch_bounds__(512) kC(
    const float* __restrict__ x,
    const float* __restrict__ twr, const float* __restrict__ twi,
    const float* __restrict__ tbr, const float* __restrict__ tbi,
    const float* __restrict__ lwr, const float* __restrict__ lwi,
    const float* __restrict__ lbr, const float* __restrict__ lbi,
    const float* __restrict__ awr, const float* __restrict__ awi,
    const float* __restrict__ abr, const float* __restrict__ abi,
    float* __restrict__ out)
{
    const int f = blockIdx.x & (FF-1);
    const int b = blockIdx.x >> 8;

    __shared__ float stwr[C8*C16*5], stwi[C8*C16*5];
    __shared__ float slwr[64], slwi[64], sawr[64], sawi[64];
    __shared__ float stbr[8], stbi[8], slbr[8], slbi[8], sabr[8], sabi[8];

    for (int i = threadIdx.x; i < C8*C16*5; i += blockDim.x) {
        stwr[i] = twr[f*C8*C16*5 + i];   // layout ((f*8+o)*16+c)*5+k
        stwi[i] = twi[f*C8*C16*5 + i];
    }
    if (threadIdx.x < 64) {
        slwr[threadIdx.x] = lwr[f*64 + threadIdx.x];  // (f*8+o)*8+c
        slwi[threadIdx.x] = lwi[f*64 + threadIdx.x];
        sawr[threadIdx.x] = awr[f*64 + threadIdx.x];
        sawi[threadIdx.x] = awi[f*64 + threadIdx.x];
    }
    if (threadIdx.x < 8) {
        stbr[threadIdx.x] = tbr[f*8 + threadIdx.x];
        stbi[threadIdx.x] = tbi[f*8 + threadIdx.x];
        slbr[threadIdx.x] = lbr[f*8 + threadIdx.x];
        slbi[threadIdx.x] = lbi[f*8 + threadIdx.x];
        sabr[threadIdx.x] = abr[f*8 + threadIdx.x];
        sabi[threadIdx.x] = abi[f*8 + threadIdx.x];
    }
    __syncthreads();

    const float* s2r  = g_s2 + (b*2+0)*C16*CHW + f*TN;
    const float* s2i  = g_s2 + (b*2+1)*C16*CHW + f*TN;
    const float* xr_p = x    + (b*2+0)*C8 *CHW + f*TN;
    const float* xi_p = x    + (b*2+1)*C8 *CHW + f*TN;
    float* outr = out + (b*2+0)*C8*CHW + f*TN;
    float* outi = out + (b*2+1)*C8*CHW + f*TN;

    for (int t = threadIdx.x; t < TN; t += blockDim.x) {
        // ---- time_conv: y[o] = bias + sum_{k,c} w[o,c,k] * v[c, t+2k] ----
        float ar[8], ai[8];
        #pragma unroll
        for (int o = 0; o < 8; o++) { ar[o] = stbr[o]; ai[o] = stbi[o]; }
        #pragma unroll
        for (int k = 0; k < 5; k++) {
            int tt = t + 2*k;
            if (tt < TN) {
                #pragma unroll
                for (int c = 0; c < C16; c++) {
                    float vr = s2r[c*CHW + tt];
                    float vi = s2i[c*CHW + tt];
                    #pragma unroll
                    for (int o = 0; o < 8; o++) {
                        ar[o] = fmaf(stwr[(o*C16 + c)*5 + k], vr, ar[o]);
                        ai[o] = fmaf(stwi[(o*C16 + c)*5 + k], vi, ai[o]);
                    }
                }
            }
        }
        // ---- cExp ----
        float er[8], ei[8];
        #pragma unroll
        for (int o = 0; o < 8; o++) {
            float r = __expf(ar[o]);
            float sn, cs;
            __sincosf(ai[o], &sn, &cs);
            er[o] = r * cs;
            ei[o] = r * sn;
        }
        // ---- last_shuffle (complex): yr = Wr*er - Wi*ei + (br-bi), etc ----
        float sr[8], si[8];
        #pragma unroll
        for (int o = 0; o < 8; o++) {
            float yr = slbr[o] - slbi[o];
            float yi = slbr[o] + slbi[o];
            #pragma unroll
            for (int c = 0; c < 8; c++) {
                float wr_ = slwr[o*8+c], wi_ = slwi[o*8+c];
                yr = fmaf(wr_, er[c], yr);
                yr = fmaf(-wi_, ei[c], yr);
                yi = fmaf(wr_, ei[c], yi);
                yi = fmaf(wi_, er[c], yi);
            }
            sr[o] = yr; si[o] = yi;
        }
        // ---- cMul with original x ----
        float mr[8], mi[8];
        #pragma unroll
        for (int c = 0; c < 8; c++) {
            float vxr = xr_p[c*CHW + t];
            float vxi = xi_p[c*CHW + t];
            mr[c] = sr[c]*vxr - si[c]*vxi;
            mi[c] = sr[c]*vxi + si[c]*vxr;
        }
        // ---- last (complex 8x8) -> output ----
        #pragma unroll
        for (int o = 0; o < 8; o++) {
            float yr = sabr[o] - sabi[o];
            float yi = sabr[o] + sabi[o];
            #pragma unroll
            for (int c = 0; c < 8; c++) {
                float wr_ = sawr[o*8+c], wi_ = sawi[o*8+c];
                yr = fmaf(wr_, mr[c], yr);
                yr = fmaf(-wi_, mi[c], yr);
                yi = fmaf(wr_, mi[c], yi);
                yi = fmaf(wi_, mr[c], yi);
            }
            outr[o*CHW + t] = yr;
            outi[o*CHW + t] = yi;
        }
    }
}

// ---------------------------------------------------------------------------
extern "C" void kernel_launch(void* const* d_in, const int* in_sizes, int n_in,
                              void* d_out, int out_size)
{
    const float* x     = (const float*)d_in[0];
    const float* cs_wr = (const float*)d_in[1];
    const float* cs_wi = (const float*)d_in[2];
    const float* cs_br = (const float*)d_in[3];
    const float* cs_bi = (const float*)d_in[4];
    const float* fc_wr = (const float*)d_in[5];
    const float* fc_wi = (const float*)d_in[6];
    const float* fc_br = (const float*)d_in[7];
    const float* fc_bi = (const float*)d_in[8];
    const float* tc_wr = (const float*)d_in[9];
    const float* tc_wi = (const float*)d_in[10];
    const float* tc_br = (const float*)d_in[11];
    const float* tc_bi = (const float*)d_in[12];
    const float* ls_wr = (const float*)d_in[13];
    const float* ls_wi = (const float*)d_in[14];
    const float* ls_br = (const float*)d_in[15];
    const float* ls_bi = (const float*)d_in[16];
    const float* la_wr = (const float*)d_in[17];
    const float* la_wi = (const float*)d_in[18];
    const float* la_br = (const float*)d_in[19];
    const float* la_bi = (const float*)d_in[20];
    float* out = (float*)d_out;

    dim3 gA((TN + 255)/256, FF, BB);
    kA<<<gA, 256>>>(x, cs_wr, cs_wi, cs_br, cs_bi);

    dim3 gB((TN + 255)/256, FF, BB*C16);
    kB<<<gB, 256>>>(fc_wr, fc_wi, fc_br, fc_bi);

    kC<<<BB*FF, 512>>>(x, tc_wr, tc_wi, tc_br, tc_bi,
                       ls_wr, ls_wi, ls_br, ls_bi,
                       la_wr, la_wi, la_br, la_bi, out);
}